// round 1
// baseline (speedup 1.0000x reference)
#include <cuda_runtime.h>
#include <cstdint>

#define Bn   2
#define Nn   2048
#define CIN  128
#define Hh   16
#define Cc   8
#define HC   128
#define TI   8
#define TJ   32
#define LOG2E 1.4426950408889634f

// ---- device scratch (no allocations allowed) ----
__device__ float g_h [Bn * Nn * HC];   // projected features  [b,n,f]
__device__ float g_lp[Bn * Nn * Hh];   // parent logits * log2e
__device__ float g_lc[Bn * Nn * Hh];   // child  logits * log2e
__device__ float g_mx[Bn * Hh];        // max_j lc' per (b,h)

// ---------------------------------------------------------------
// Kernel 1: h = node_feats @ W + b   (4096x128 @ 128x128)
// 256 blocks x 128 threads, 16 rows per block.
// ---------------------------------------------------------------
__global__ __launch_bounds__(128) void k_proj(const float* __restrict__ nf,
                                              const float* __restrict__ W,
                                              const float* __restrict__ bias) {
    __shared__ float snf[16][CIN];
    const int t  = threadIdx.x;
    const int r0 = blockIdx.x * 16;
#pragma unroll
    for (int r = 0; r < 16; ++r)
        snf[r][t] = nf[(size_t)(r0 + r) * CIN + t];
    __syncthreads();

    float acc[16];
    const float bv = bias[t];
#pragma unroll
    for (int r = 0; r < 16; ++r) acc[r] = bv;

    for (int k4 = 0; k4 < CIN / 4; ++k4) {
        const float w0 = W[(k4 * 4 + 0) * HC + t];
        const float w1 = W[(k4 * 4 + 1) * HC + t];
        const float w2 = W[(k4 * 4 + 2) * HC + t];
        const float w3 = W[(k4 * 4 + 3) * HC + t];
#pragma unroll
        for (int r = 0; r < 16; ++r) {
            const float4 s = *(const float4*)&snf[r][k4 * 4];
            acc[r] = fmaf(s.x, w0, acc[r]);
            acc[r] = fmaf(s.y, w1, acc[r]);
            acc[r] = fmaf(s.z, w2, acc[r]);
            acc[r] = fmaf(s.w, w3, acc[r]);
        }
    }
#pragma unroll
    for (int r = 0; r < 16; ++r)
        g_h[(size_t)(r0 + r) * HC + t] = acc[r];
}

// ---------------------------------------------------------------
// Kernel 2: lp/lc per (n, head), pre-scaled by log2(e)
// ---------------------------------------------------------------
__global__ __launch_bounds__(256) void k_lplc(const float* __restrict__ a) {
    const int idx = blockIdx.x * 256 + threadIdx.x;   // < Bn*Nn*Hh
    const int n  = idx >> 4;
    const int hh = idx & 15;
    const float* hp = g_h + (size_t)n * HC + hh * Cc;
    const float* ap = a + hh * 2 * Cc;
    float lp = 0.f, lc = 0.f;
#pragma unroll
    for (int c = 0; c < Cc; ++c) {
        const float hv = hp[c];
        lp = fmaf(hv, ap[c],      lp);
        lc = fmaf(hv, ap[Cc + c], lc);
    }
    g_lp[idx] = lp * LOG2E;
    g_lc[idx] = lc * LOG2E;
}

// ---------------------------------------------------------------
// Kernel 3: max_j lc'[b, j, h]  (32 blocks, one per (b,h))
// ---------------------------------------------------------------
__global__ __launch_bounds__(256) void k_max() {
    const int b  = blockIdx.x >> 4;
    const int hh = blockIdx.x & 15;
    float m = -1e30f;
    for (int n = threadIdx.x; n < Nn; n += 256)
        m = fmaxf(m, g_lc[((size_t)b * Nn + n) * Hh + hh]);
    __shared__ float red[256];
    red[threadIdx.x] = m;
    __syncthreads();
    for (int s = 128; s; s >>= 1) {
        if (threadIdx.x < s)
            red[threadIdx.x] = fmaxf(red[threadIdx.x], red[threadIdx.x + s]);
        __syncthreads();
    }
    if (threadIdx.x == 0) g_mx[blockIdx.x] = red[0];
}

// ---------------------------------------------------------------
// Kernel 4: fused masked-softmax attention + aggregation.
// Block = 512 threads (warp == head), TI=8 query rows / block.
// ---------------------------------------------------------------
__global__ __launch_bounds__(512, 1) void k_main(const float* __restrict__ adj,
                                                 float* __restrict__ out) {
    __shared__ float4 hs4[TJ * 32];      // [j][fq^swz], 16 KB
    __shared__ float  slc[Hh * 33];      // [h][j] padded

    const int t    = threadIdx.x;
    const int warp = t >> 5;
    const int lane = t & 31;
    const int hh   = warp;

    const int b  = blockIdx.x >> 8;               // Nn/TI = 256 blocks per batch
    const int i0 = (blockIdx.x & 255) * TI;
    const size_t bN = (size_t)b * Nn;

    // per-row constants: A = lp' - m',  Bv = 0.2*lp' - m'
    float A[TI], Bv[TI];
    {
        const float mx = g_mx[b * Hh + hh];
#pragma unroll
        for (int r = 0; r < TI; ++r) {
            const float lp = g_lp[(bN + i0 + r) * Hh + hh];
            const float s  = lp + mx;
            const float mp = fmaxf(s, 0.2f * s);   // leaky upper bound
            A[r]  = lp - mp;
            Bv[r] = 0.2f * lp - mp;
        }
    }

    float den[TI];
    float num[TI][Cc];
#pragma unroll
    for (int r = 0; r < TI; ++r) {
        den[r] = 0.f;
#pragma unroll
        for (int c = 0; c < Cc; ++c) num[r][c] = 0.f;
    }

    for (int j0 = 0; j0 < Nn; j0 += TJ) {
        __syncthreads();
        // ---- stage h tile (32 rows x 128 feats) with XOR swizzle ----
#pragma unroll
        for (int pass = 0; pass < 2; ++pass) {
            const int jl = pass * 16 + warp;
            const float4 v = *((const float4*)(g_h + (bN + j0 + jl) * HC) + lane);
            hs4[jl * 32 + (lane ^ (jl & 7))] = v;
        }
        // ---- stage lc tile ----
        {
            const int nl = t >> 4, hq = t & 15;
            slc[hq * 33 + nl] = g_lc[(bN + j0 + nl) * Hh + hq];
        }
        __syncthreads();

        const float4 fA = hs4[lane * 32 + ((2 * hh)     ^ (lane & 7))];
        const float4 fB = hs4[lane * 32 + ((2 * hh + 1) ^ (lane & 7))];
        const float  lcv  = slc[hh * 33 + lane];
        const float  lcv2 = 0.2f * lcv;

        float aj[TI];
#pragma unroll
        for (int r = 0; r < TI; ++r)
            aj[r] = __ldg(&adj[(bN + i0 + r) * (size_t)Nn + j0 + lane]);

#pragma unroll
        for (int r = 0; r < TI; ++r) {
            // v = leaky(lp'+lc') - m'  (<= 0)
            float v = fmaxf(A[r] + lcv, Bv[r] + lcv2);
            v = fmaxf(v, -80.f);
            // exp2(v) via magic round + deg-4 poly + exponent splice
            const float rr = __fadd_rn(v, 12582912.f);
            const float fr = __fadd_rn(v, -__fadd_rn(rr, -12582912.f));
            float p = 0.0096181291f;
            p = fmaf(p, fr, 0.0555041086f);
            p = fmaf(p, fr, 0.2402265069f);
            p = fmaf(p, fr, 0.6931471806f);
            p = fmaf(p, fr, 1.0f);
            const int sc = (int)((unsigned)__float_as_int(rr) << 23);
            const float e = __int_as_float(__float_as_int(p) + sc);
            const float w = aj[r] * e;
            den[r] += w;
            num[r][0] = fmaf(w, fA.x, num[r][0]);
            num[r][1] = fmaf(w, fA.y, num[r][1]);
            num[r][2] = fmaf(w, fA.z, num[r][2]);
            num[r][3] = fmaf(w, fA.w, num[r][3]);
            num[r][4] = fmaf(w, fB.x, num[r][4]);
            num[r][5] = fmaf(w, fB.y, num[r][5]);
            num[r][6] = fmaf(w, fB.z, num[r][6]);
            num[r][7] = fmaf(w, fB.w, num[r][7]);
        }
    }

    // ---- reduce over lanes (j) ----
#pragma unroll
    for (int r = 0; r < TI; ++r) {
#pragma unroll
        for (int o = 16; o; o >>= 1)
            den[r] += __shfl_xor_sync(0xffffffffu, den[r], o);
#pragma unroll
        for (int c = 0; c < Cc; ++c) {
#pragma unroll
            for (int o = 16; o; o >>= 1)
                num[r][c] += __shfl_xor_sync(0xffffffffu, num[r][c], o);
        }
    }

    if (lane == 0) {
#pragma unroll
        for (int r = 0; r < TI; ++r) {
            const float inv = 1.0f / den[r];
            float4 o0 = make_float4(num[r][0] * inv, num[r][1] * inv,
                                    num[r][2] * inv, num[r][3] * inv);
            float4 o1 = make_float4(num[r][4] * inv, num[r][5] * inv,
                                    num[r][6] * inv, num[r][7] * inv);
            float4* dst = (float4*)(out + (bN + i0 + r) * HC + hh * Cc);
            dst[0] = o0;
            dst[1] = o1;
        }
    }
}

// ---------------------------------------------------------------
extern "C" void kernel_launch(void* const* d_in, const int* in_sizes, int n_in,
                              void* d_out, int out_size) {
    const float* nf   = (const float*)d_in[0];
    const float* adj  = (const float*)d_in[1];
    const float* W    = (const float*)d_in[2];
    const float* bias = (const float*)d_in[3];
    const float* a    = (const float*)d_in[4];
    float* out = (float*)d_out;

    k_proj<<<Bn * Nn / 16, 128>>>(nf, W, bias);
    k_lplc<<<Bn * Nn * Hh / 256, 256>>>(a);
    k_max<<<Bn * Hh, 256>>>();
    k_main<<<Bn * (Nn / TI), 512>>>(adj, out);

    const long long outel = (long long)Bn * Nn * HC;        // 524288
    const long long adjel = (long long)Bn * Nn * Nn;        // 8388608
    if ((long long)out_size >= outel + adjel) {
        // reference returns (out, adj_matrix) — copy adj into the tail
        cudaMemcpyAsync(out + outel, adj, (size_t)adjel * sizeof(float),
                        cudaMemcpyDeviceToDevice);
    }
}

// round 2
// speedup vs baseline: 1.4636x; 1.4636x over previous
#include <cuda_runtime.h>
#include <cstdint>

#define Bn   2
#define Nn   2048
#define CIN  128
#define Hh   16
#define Cc   8
#define HC   128
#define TI   8
#define TJ   64
#define NTILE (Nn / TJ)          // 32
#define LOG2E 1.4426950408889634f

// per-buffer smem (floats): h tile 64*128 = 8192, adj tile 8*64 = 512
#define BUF_FLOATS (64 * 128 + 512)
#define SMEM_BYTES (2 * BUF_FLOATS * 4)

// ---- device scratch ----
__device__ float g_h  [Bn * Nn * HC];
__device__ float g_lp [Bn * Nn * Hh];
__device__ float g_lc [Bn * Nn * Hh];
__device__ float g_lcT[Bn * Hh * Nn];   // transposed: [b][h][n], *LOG2E
__device__ float g_mx [Bn * Hh];

// ---- PTX helpers ----
#define PACK2(d, lo, hi)  asm("mov.b64 %0, {%1,%2};" : "=l"(d) : "f"(lo), "f"(hi))
#define UNPACK2(lo, hi, s) asm("mov.b64 {%0,%1}, %2;" : "=f"(lo), "=f"(hi) : "l"(s))
#define FFMA2(acc, x, y)  asm("fma.rn.f32x2 %0, %1, %2, %0;" : "+l"(acc) : "l"(x), "l"(y))
#define EX2(d, s)         asm("ex2.approx.f32 %0, %1;" : "=f"(d) : "f"(s))
#define CP16(dst, src) asm volatile("cp.async.cg.shared.global [%0], [%1], 16;" :: "r"(dst), "l"(src))
#define CP4(dst, src)  asm volatile("cp.async.ca.shared.global [%0], [%1], 4;"  :: "r"(dst), "l"(src))
#define CP_COMMIT()    asm volatile("cp.async.commit_group;")
#define CP_WAIT(n)     asm volatile("cp.async.wait_group %0;" :: "n"(n))

static __device__ __forceinline__ uint32_t s2u(const void* p) {
    return (uint32_t)__cvta_generic_to_shared(p);
}

// ---------------------------------------------------------------
// Kernel 1: h = node_feats @ W + b
// ---------------------------------------------------------------
__global__ __launch_bounds__(128) void k_proj(const float* __restrict__ nf,
                                              const float* __restrict__ W,
                                              const float* __restrict__ bias) {
    __shared__ float snf[16][CIN];
    const int t  = threadIdx.x;
    const int r0 = blockIdx.x * 16;
#pragma unroll
    for (int r = 0; r < 16; ++r)
        snf[r][t] = nf[(size_t)(r0 + r) * CIN + t];
    __syncthreads();

    float acc[16];
    const float bv = bias[t];
#pragma unroll
    for (int r = 0; r < 16; ++r) acc[r] = bv;

    for (int k4 = 0; k4 < CIN / 4; ++k4) {
        const float w0 = W[(k4 * 4 + 0) * HC + t];
        const float w1 = W[(k4 * 4 + 1) * HC + t];
        const float w2 = W[(k4 * 4 + 2) * HC + t];
        const float w3 = W[(k4 * 4 + 3) * HC + t];
#pragma unroll
        for (int r = 0; r < 16; ++r) {
            const float4 s = *(const float4*)&snf[r][k4 * 4];
            acc[r] = fmaf(s.x, w0, acc[r]);
            acc[r] = fmaf(s.y, w1, acc[r]);
            acc[r] = fmaf(s.z, w2, acc[r]);
            acc[r] = fmaf(s.w, w3, acc[r]);
        }
    }
#pragma unroll
    for (int r = 0; r < 16; ++r)
        g_h[(size_t)(r0 + r) * HC + t] = acc[r];
}

// ---------------------------------------------------------------
// Kernel 2: lp/lc per (n, head), pre-scaled by log2(e); also lcT
// ---------------------------------------------------------------
__global__ __launch_bounds__(256) void k_lplc(const float* __restrict__ a) {
    const int idx = blockIdx.x * 256 + threadIdx.x;   // < Bn*Nn*Hh
    const int n  = idx >> 4;                          // global (b*Nn + n)
    const int hh = idx & 15;
    const float* hp = g_h + (size_t)n * HC + hh * Cc;
    const float* ap = a + hh * 2 * Cc;
    float lp = 0.f, lc = 0.f;
#pragma unroll
    for (int c = 0; c < Cc; ++c) {
        const float hv = hp[c];
        lp = fmaf(hv, ap[c],      lp);
        lc = fmaf(hv, ap[Cc + c], lc);
    }
    lp *= LOG2E; lc *= LOG2E;
    g_lp[idx] = lp;
    g_lc[idx] = lc;
    const int b  = n >> 11;
    const int nn = n & (Nn - 1);
    g_lcT[((size_t)b * Hh + hh) * Nn + nn] = lc;
}

// ---------------------------------------------------------------
// Kernel 3: max_j lc'[b, j, h]
// ---------------------------------------------------------------
__global__ __launch_bounds__(256) void k_max() {
    const int b  = blockIdx.x >> 4;
    const int hh = blockIdx.x & 15;
    float m = -1e30f;
    for (int n = threadIdx.x; n < Nn; n += 256)
        m = fmaxf(m, g_lc[((size_t)b * Nn + n) * Hh + hh]);
    __shared__ float red[256];
    red[threadIdx.x] = m;
    __syncthreads();
    for (int s = 128; s; s >>= 1) {
        if (threadIdx.x < s)
            red[threadIdx.x] = fmaxf(red[threadIdx.x], red[threadIdx.x + s]);
        __syncthreads();
    }
    if (threadIdx.x == 0) g_mx[blockIdx.x] = red[0];
}

// ---------------------------------------------------------------
// Kernel 4: fused masked-softmax attention + aggregation.
// 512 threads (warp == head), TI=8 rows, TJ=64 (lane owns j=lane, lane+32).
// cp.async double-buffered staging, MUFU exp2, packed f32x2 aggregation.
// ---------------------------------------------------------------
__global__ __launch_bounds__(512, 1) void k_main(const float* __restrict__ adj,
                                                 float* __restrict__ out) {
    extern __shared__ float smem[];

    const int t    = threadIdx.x;
    const int warp = t >> 5;
    const int lane = t & 31;
    const int hh   = warp;

    const int b  = blockIdx.x >> 8;
    const int i0 = (blockIdx.x & 255) * TI;
    const size_t bN = (size_t)b * Nn;

    float* const buf0 = smem;
    float* const buf1 = smem + BUF_FLOATS;

    // ---- staging helper (each thread: 4x16B h + 1x4B adj) ----
    auto stage = [&](int tile, float* buf) {
        const int j0 = tile * TJ;
        float4* hb = (float4*)buf;
#pragma unroll
        for (int q = 0; q < 4; ++q) {
            const int id = q * 512 + t;
            const int j  = id >> 5;
            const int c4 = id & 31;
            const float4* src = (const float4*)(g_h + (bN + j0 + j) * HC) + c4;
            CP16(s2u(hb + (j * 32 + (c4 ^ (j & 7)))), src);
        }
        {
            const int r = t >> 6, j = t & 63;
            const float* src = adj + (bN + i0 + r) * (size_t)Nn + j0 + j;
            CP4(s2u(buf + 8192 + t), src);
        }
    };

    // per-row constants: A = lp' - m',  Bv = 0.2*lp' - m'
    float A[TI], Bv[TI];
    {
        const float mx = g_mx[b * Hh + hh];
#pragma unroll
        for (int r = 0; r < TI; ++r) {
            const float lp = g_lp[(bN + i0 + r) * Hh + hh];
            const float s  = lp + mx;
            const float mp = fmaxf(s, 0.2f * s);
            A[r]  = lp - mp;
            Bv[r] = 0.2f * lp - mp;
        }
    }

    unsigned long long num2[TI][4];
    float den[TI];
#pragma unroll
    for (int r = 0; r < TI; ++r) {
        den[r] = 0.f;
#pragma unroll
        for (int c = 0; c < 4; ++c) num2[r][c] = 0ull;
    }

    const float* lcT = g_lcT + ((size_t)b * Hh + hh) * Nn;
    const int c4A = 2 * hh, c4B = 2 * hh + 1;
    const int swz = lane & 7;

    stage(0, buf0);
    CP_COMMIT();

    for (int tt = 0; tt < NTILE; ++tt) {
        float* const buf = (tt & 1) ? buf1 : buf0;
        if (tt + 1 < NTILE) {
            stage(tt + 1, (tt & 1) ? buf0 : buf1);
            CP_COMMIT();
            CP_WAIT(1);
        } else {
            CP_WAIT(0);
        }
        __syncthreads();

        const int j0 = tt * TJ;
        const float lc0 = __ldg(lcT + j0 + lane);
        const float lc1 = __ldg(lcT + j0 + lane + 32);
        const float4* hb = (const float4*)buf;
        const float4 fa0 = hb[lane * 32        + (c4A ^ swz)];
        const float4 fb0 = hb[lane * 32        + (c4B ^ swz)];
        const float4 fa1 = hb[(lane + 32) * 32 + (c4A ^ swz)];
        const float4 fb1 = hb[(lane + 32) * 32 + (c4B ^ swz)];
        unsigned long long pA00, pA01, pB00, pB01, pA10, pA11, pB10, pB11;
        PACK2(pA00, fa0.x, fa0.y); PACK2(pA01, fa0.z, fa0.w);
        PACK2(pB00, fb0.x, fb0.y); PACK2(pB01, fb0.z, fb0.w);
        PACK2(pA10, fa1.x, fa1.y); PACK2(pA11, fa1.z, fa1.w);
        PACK2(pB10, fb1.x, fb1.y); PACK2(pB11, fb1.z, fb1.w);
        const float l0 = lc0, l0s = 0.2f * lc0;
        const float l1 = lc1, l1s = 0.2f * lc1;
        const float* ab = buf + 8192;

        float aj0[TI], aj1[TI];
#pragma unroll
        for (int r = 0; r < TI; ++r) {
            aj0[r] = ab[r * 64 + lane];
            aj1[r] = ab[r * 64 + lane + 32];
        }

#pragma unroll
        for (int r = 0; r < TI; ++r) {
            const float v0 = fmaxf(A[r] + l0, Bv[r] + l0s);
            const float v1 = fmaxf(A[r] + l1, Bv[r] + l1s);
            float e0, e1;
            EX2(e0, v0); EX2(e1, v1);
            const float w0 = aj0[r] * e0;
            const float w1 = aj1[r] * e1;
            den[r] += w0 + w1;
            unsigned long long w00, w11;
            PACK2(w00, w0, w0); PACK2(w11, w1, w1);
            FFMA2(num2[r][0], w00, pA00); FFMA2(num2[r][0], w11, pA10);
            FFMA2(num2[r][1], w00, pA01); FFMA2(num2[r][1], w11, pA11);
            FFMA2(num2[r][2], w00, pB00); FFMA2(num2[r][2], w11, pB10);
            FFMA2(num2[r][3], w00, pB01); FFMA2(num2[r][3], w11, pB11);
        }
        __syncthreads();
    }

    // ---- reduce over lanes (j) and write ----
#pragma unroll
    for (int r = 0; r < TI; ++r) {
        float nf[8];
        UNPACK2(nf[0], nf[1], num2[r][0]);
        UNPACK2(nf[2], nf[3], num2[r][1]);
        UNPACK2(nf[4], nf[5], num2[r][2]);
        UNPACK2(nf[6], nf[7], num2[r][3]);
        float d = den[r];
#pragma unroll
        for (int o = 16; o; o >>= 1) {
            d += __shfl_xor_sync(0xffffffffu, d, o);
#pragma unroll
            for (int c = 0; c < 8; ++c)
                nf[c] += __shfl_xor_sync(0xffffffffu, nf[c], o);
        }
        if (lane == 0) {
            const float inv = 1.0f / d;
            float4 o0 = make_float4(nf[0] * inv, nf[1] * inv, nf[2] * inv, nf[3] * inv);
            float4 o1 = make_float4(nf[4] * inv, nf[5] * inv, nf[6] * inv, nf[7] * inv);
            float4* dst = (float4*)(out + (bN + i0 + r) * HC + hh * Cc);
            dst[0] = o0;
            dst[1] = o1;
        }
    }
}

// ---------------------------------------------------------------
extern "C" void kernel_launch(void* const* d_in, const int* in_sizes, int n_in,
                              void* d_out, int out_size) {
    const float* nf   = (const float*)d_in[0];
    const float* adj  = (const float*)d_in[1];
    const float* W    = (const float*)d_in[2];
    const float* bias = (const float*)d_in[3];
    const float* a    = (const float*)d_in[4];
    float* out = (float*)d_out;

    cudaFuncSetAttribute(k_main, cudaFuncAttributeMaxDynamicSharedMemorySize,
                         SMEM_BYTES);

    k_proj<<<Bn * Nn / 16, 128>>>(nf, W, bias);
    k_lplc<<<Bn * Nn * Hh / 256, 256>>>(a);
    k_max<<<Bn * Hh, 256>>>();
    k_main<<<Bn * (Nn / TI), 512, SMEM_BYTES>>>(adj, out);

    const long long outel = (long long)Bn * Nn * HC;        // 524288
    const long long adjel = (long long)Bn * Nn * Nn;        // 8388608
    if ((long long)out_size >= outel + adjel) {
        cudaMemcpyAsync(out + outel, adj, (size_t)adjel * sizeof(float),
                        cudaMemcpyDeviceToDevice);
    }
}

// round 3
// speedup vs baseline: 2.7000x; 1.8448x over previous
#include <cuda_runtime.h>
#include <cuda_fp16.h>
#include <cstdint>

#define Bn   2
#define Nn   2048
#define CIN  128
#define Hh   16
#define Cc   8
#define HC   128
#define LOG2E 1.4426950408889634f
#define NJB  16          // j-blocks of 128
#define ADJ_STRIDE 136   // padded row stride (floats) for conflict-free LDS.64

// ---- device scratch ----
__device__ float  g_h  [Bn * Nn * HC];
__device__ __half g_hT [Bn * HC * Nn];   // [b][f][n] fp16, transposed
__device__ float  g_lp [Bn * Nn * Hh];
__device__ float  g_lc [Bn * Nn * Hh];
__device__ float  g_lcT[Bn * Hh * Nn];   // [b][h][n], *LOG2E
__device__ float  g_mx [Bn * Hh];

// ---- PTX helpers ----
#define CP16(dst, src) asm volatile("cp.async.cg.shared.global [%0], [%1], 16;" :: "r"(dst), "l"(src))
#define CP_COMMIT()    asm volatile("cp.async.commit_group;")
#define CP_WAIT(n)     asm volatile("cp.async.wait_group %0;" :: "n"(n))

static __device__ __forceinline__ uint32_t s2u(const void* p) {
    return (uint32_t)__cvta_generic_to_shared(p);
}
static __device__ __forceinline__ float ex2f(float x) {
    float r; asm("ex2.approx.f32 %0, %1;" : "=f"(r) : "f"(x)); return r;
}
static __device__ __forceinline__ uint32_t packh2(float lo, float hi) {
    uint32_t d; asm("cvt.rn.f16x2.f32 %0, %1, %2;" : "=r"(d) : "f"(hi), "f"(lo)); return d;
}
static __device__ __forceinline__ void mma16816(float& d0, float& d1, float& d2, float& d3,
                                                uint32_t a0, uint32_t a1, uint32_t a2, uint32_t a3,
                                                uint32_t b0, uint32_t b1) {
    asm("mma.sync.aligned.m16n8k16.row.col.f32.f16.f16.f32 "
        "{%0,%1,%2,%3}, {%4,%5,%6,%7}, {%8,%9}, {%0,%1,%2,%3};"
        : "+f"(d0), "+f"(d1), "+f"(d2), "+f"(d3)
        : "r"(a0), "r"(a1), "r"(a2), "r"(a3), "r"(b0), "r"(b1));
}

// ---------------------------------------------------------------
// Kernel 1: h = node_feats @ W + b ; also fp16 transposed copy
// ---------------------------------------------------------------
__global__ __launch_bounds__(128) void k_proj(const float* __restrict__ nf,
                                              const float* __restrict__ W,
                                              const float* __restrict__ bias) {
    __shared__ float snf[16][CIN];
    const int t  = threadIdx.x;
    const int r0 = blockIdx.x * 16;
#pragma unroll
    for (int r = 0; r < 16; ++r)
        snf[r][t] = nf[(size_t)(r0 + r) * CIN + t];
    __syncthreads();

    float acc[16];
    const float bv = bias[t];
#pragma unroll
    for (int r = 0; r < 16; ++r) acc[r] = bv;

    for (int k4 = 0; k4 < CIN / 4; ++k4) {
        const float w0 = W[(k4 * 4 + 0) * HC + t];
        const float w1 = W[(k4 * 4 + 1) * HC + t];
        const float w2 = W[(k4 * 4 + 2) * HC + t];
        const float w3 = W[(k4 * 4 + 3) * HC + t];
#pragma unroll
        for (int r = 0; r < 16; ++r) {
            const float4 s = *(const float4*)&snf[r][k4 * 4];
            acc[r] = fmaf(s.x, w0, acc[r]);
            acc[r] = fmaf(s.y, w1, acc[r]);
            acc[r] = fmaf(s.z, w2, acc[r]);
            acc[r] = fmaf(s.w, w3, acc[r]);
        }
    }
#pragma unroll
    for (int r = 0; r < 16; ++r) {
        const int n  = r0 + r;
        const int b  = n >> 11;
        const int nn = n & (Nn - 1);
        g_h[(size_t)n * HC + t] = acc[r];
        g_hT[((size_t)b * HC + t) * Nn + nn] = __float2half(acc[r]);
    }
}

// ---------------------------------------------------------------
// Kernel 2: lp/lc per (n, head), pre-scaled by log2(e); also lcT
// ---------------------------------------------------------------
__global__ __launch_bounds__(256) void k_lplc(const float* __restrict__ a) {
    const int idx = blockIdx.x * 256 + threadIdx.x;
    const int n  = idx >> 4;
    const int hh = idx & 15;
    const float* hp = g_h + (size_t)n * HC + hh * Cc;
    const float* ap = a + hh * 2 * Cc;
    float lp = 0.f, lc = 0.f;
#pragma unroll
    for (int c = 0; c < Cc; ++c) {
        const float hv = hp[c];
        lp = fmaf(hv, ap[c],      lp);
        lc = fmaf(hv, ap[Cc + c], lc);
    }
    lp *= LOG2E; lc *= LOG2E;
    g_lp[idx] = lp;
    g_lc[idx] = lc;
    const int b  = n >> 11;
    const int nn = n & (Nn - 1);
    g_lcT[((size_t)b * Hh + hh) * Nn + nn] = lc;
}

// ---------------------------------------------------------------
// Kernel 3: max_j lc'[b, j, h]
// ---------------------------------------------------------------
__global__ __launch_bounds__(256) void k_max() {
    const int b  = blockIdx.x >> 4;
    const int hh = blockIdx.x & 15;
    float m = -1e30f;
    for (int n = threadIdx.x; n < Nn; n += 256)
        m = fmaxf(m, g_lc[((size_t)b * Nn + n) * Hh + hh]);
    __shared__ float red[256];
    red[threadIdx.x] = m;
    __syncthreads();
    for (int s = 128; s; s >>= 1) {
        if (threadIdx.x < s)
            red[threadIdx.x] = fmaxf(red[threadIdx.x], red[threadIdx.x + s]);
        __syncthreads();
    }
    if (threadIdx.x == 0) g_mx[blockIdx.x] = red[0];
}

// ---------------------------------------------------------------
// Kernel 4: fused softmax-attention via mma.m16n8k16.
// 512 threads = 16 warps (warp == head), i-tile = 16 rows/block.
// w(i,j) computed straight into the A-fragment layout; B = h (fp16,
// transposed) for the numerator, B = ones for the denominator.
// adj tile (16 x 128) double-buffered via cp.async.
// ---------------------------------------------------------------
__global__ __launch_bounds__(512, 2) void k_main(const float* __restrict__ adj,
                                                 float* __restrict__ out,
                                                 int copy_adj) {
    __shared__ float sadj[2][16][ADJ_STRIDE];

    const int t    = threadIdx.x;
    const int warp = t >> 5;
    const int lane = t & 31;
    const int gid  = lane >> 2;   // 0..7
    const int tig  = lane & 3;    // 0..3
    const int hh   = warp;

    const int b  = blockIdx.x >> 7;          // 128 i-blocks per batch
    const int i0 = (blockIdx.x & 127) * 16;
    const size_t bN = (size_t)b * Nn;

    // per-row constants (rows r0 = i0+gid, r1 = r0+8)
    float A0, B0, A1, B1;
    {
        const float mx  = g_mx[b * Hh + hh];
        const float lp0 = g_lp[(bN + i0 + gid)     * Hh + hh];
        const float lp1 = g_lp[(bN + i0 + gid + 8) * Hh + hh];
        const float s0 = lp0 + mx, s1 = lp1 + mx;
        const float m0 = fmaxf(s0, 0.2f * s0);
        const float m1 = fmaxf(s1, 0.2f * s1);
        A0 = lp0 - m0;  B0 = 0.2f * lp0 - m0;
        A1 = lp1 - m1;  B1 = 0.2f * lp1 - m1;
    }

    const float*  lcT = g_lcT + ((size_t)b * Hh + hh) * Nn;
    const __half* hTp = g_hT + ((size_t)b * HC + hh * Cc + gid) * Nn;
    const float*  adjrow = adj + (bN + i0) * (size_t)Nn;

    float dn0 = 0.f, dn1 = 0.f, dn2 = 0.f, dn3 = 0.f;   // numerator
    float dd0 = 0.f, dd1 = 0.f, dd2 = 0.f, dd3 = 0.f;   // denominator
    const uint32_t ONES = 0x3C003C00u;                   // half2(1,1)

    // ---- adj staging: 16 rows x 128 cols per j-block, 1 CP16/thread ----
    auto stage = [&](int jb, int bufi) {
        const int row = t >> 5, c4 = t & 31;
        const float* src = adjrow + (size_t)row * Nn + jb * 128 + c4 * 4;
        CP16(s2u(&sadj[bufi][row][c4 * 4]), src);
    };

    stage(0, 0);
    CP_COMMIT();

    for (int jb = 0; jb < NJB; ++jb) {
        if (jb + 1 < NJB) { stage(jb + 1, (jb + 1) & 1); CP_COMMIT(); CP_WAIT(1); }
        else              { CP_WAIT(0); }
        __syncthreads();
        const float (*sa)[ADJ_STRIDE] = sadj[jb & 1];

#pragma unroll 2
        for (int ks = 0; ks < 8; ++ks) {
            const int jc = ks * 16 + 2 * tig;       // col within j-block
            const int j  = jb * 128 + jc;           // global j (k-dim)

            const float2 lcl = *(const float2*)(lcT + j);
            const float2 lch = *(const float2*)(lcT + j + 8);
            const uint32_t bh0 = *(const uint32_t*)(hTp + j);
            const uint32_t bh1 = *(const uint32_t*)(hTp + j + 8);
            const float2 a00 = *(const float2*)&sa[gid    ][jc];
            const float2 a01 = *(const float2*)&sa[gid    ][jc + 8];
            const float2 a10 = *(const float2*)&sa[gid + 8][jc];
            const float2 a11 = *(const float2*)&sa[gid + 8][jc + 8];

            const float lsx = 0.2f * lcl.x, lsy = 0.2f * lcl.y;
            const float lhx = 0.2f * lch.x, lhy = 0.2f * lch.y;

            const float w00x = a00.x * ex2f(fmaxf(A0 + lcl.x, B0 + lsx));
            const float w00y = a00.y * ex2f(fmaxf(A0 + lcl.y, B0 + lsy));
            const float w01x = a01.x * ex2f(fmaxf(A0 + lch.x, B0 + lhx));
            const float w01y = a01.y * ex2f(fmaxf(A0 + lch.y, B0 + lhy));
            const float w10x = a10.x * ex2f(fmaxf(A1 + lcl.x, B1 + lsx));
            const float w10y = a10.y * ex2f(fmaxf(A1 + lcl.y, B1 + lsy));
            const float w11x = a11.x * ex2f(fmaxf(A1 + lch.x, B1 + lhx));
            const float w11y = a11.y * ex2f(fmaxf(A1 + lch.y, B1 + lhy));

            const uint32_t ra0 = packh2(w00x, w00y);   // row0, cols lo
            const uint32_t ra1 = packh2(w10x, w10y);   // row1, cols lo
            const uint32_t ra2 = packh2(w01x, w01y);   // row0, cols hi
            const uint32_t ra3 = packh2(w11x, w11y);   // row1, cols hi

            mma16816(dn0, dn1, dn2, dn3, ra0, ra1, ra2, ra3, bh0, bh1);
            mma16816(dd0, dd1, dd2, dd3, ra0, ra1, ra2, ra3, ONES, ONES);
        }
        __syncthreads();
    }

    // ---- epilogue: divide and store ----
    {
        const float inv0 = 1.0f / dd0;   // row r0 (all den cols equal)
        const float inv1 = 1.0f / dd2;   // row r1
        float2 o0 = make_float2(dn0 * inv0, dn1 * inv0);
        float2 o1 = make_float2(dn2 * inv1, dn3 * inv1);
        *(float2*)(out + (bN + i0 + gid)     * HC + hh * Cc + 2 * tig) = o0;
        *(float2*)(out + (bN + i0 + gid + 8) * HC + hh * Cc + 2 * tig) = o1;
    }

    // ---- fold adj tail copy into this kernel ----
    if (copy_adj) {
        float* dst = out + (size_t)Bn * Nn * HC + (bN + i0) * (size_t)Nn;
        const float4* s4 = (const float4*)adjrow;
        float4* d4 = (float4*)dst;
#pragma unroll
        for (int q = 0; q < 16; ++q)
            d4[q * 512 + t] = s4[q * 512 + t];
    }
}

// ---------------------------------------------------------------
extern "C" void kernel_launch(void* const* d_in, const int* in_sizes, int n_in,
                              void* d_out, int out_size) {
    const float* nf   = (const float*)d_in[0];
    const float* adj  = (const float*)d_in[1];
    const float* W    = (const float*)d_in[2];
    const float* bias = (const float*)d_in[3];
    const float* a    = (const float*)d_in[4];
    float* out = (float*)d_out;

    const long long outel = (long long)Bn * Nn * HC;        // 524288
    const long long adjel = (long long)Bn * Nn * Nn;        // 8388608
    const int copy_adj = ((long long)out_size >= outel + adjel) ? 1 : 0;

    k_proj<<<Bn * Nn / 16, 128>>>(nf, W, bias);
    k_lplc<<<Bn * Nn * Hh / 256, 256>>>(a);
    k_max<<<Bn * Hh, 256>>>();
    k_main<<<Bn * (Nn / 16), 512>>>(adj, out, copy_adj);
}

// round 4
// speedup vs baseline: 2.7581x; 1.0215x over previous
#include <cuda_runtime.h>
#include <cuda_fp16.h>
#include <cstdint>

#define Bn   2
#define Nn   2048
#define CIN  128
#define Hh   16
#define Cc   8
#define HC   128
#define LOG2E 1.4426950408889634f
#define NJB  16          // j-blocks of 128
#define ADJ_STRIDE 136   // padded row stride (floats)

// ---- device scratch ----
__device__ float  g_h  [Bn * Nn * HC];
__device__ __half g_hT [Bn * HC * Nn];   // [b][f][n] fp16, transposed
__device__ float  g_lp [Bn * Nn * Hh];
__device__ float  g_lc [Bn * Nn * Hh];
__device__ __half g_F  [Bn * Hh * Nn];   // 2^(lc)      [b][h][n]
__device__ __half g_Fp [Bn * Hh * Nn];   // 2^(0.2*lc)  [b][h][n]
__device__ float  g_mx [Bn * Hh];

// ---- PTX helpers ----
#define CP16(dst, src) asm volatile("cp.async.cg.shared.global [%0], [%1], 16;" :: "r"(dst), "l"(src))
#define CP_COMMIT()    asm volatile("cp.async.commit_group;")
#define CP_WAIT(n)     asm volatile("cp.async.wait_group %0;" :: "n"(n))

static __device__ __forceinline__ uint32_t s2u(const void* p) {
    return (uint32_t)__cvta_generic_to_shared(p);
}
static __device__ __forceinline__ float ex2f(float x) {
    float r; asm("ex2.approx.f32 %0, %1;" : "=f"(r) : "f"(x)); return r;
}
static __device__ __forceinline__ uint32_t packh2(float lo, float hi) {
    uint32_t d; asm("cvt.rn.f16x2.f32 %0, %1, %2;" : "=r"(d) : "f"(hi), "f"(lo)); return d;
}
static __device__ __forceinline__ uint32_t h2b(__half2 v) {
    return *reinterpret_cast<uint32_t*>(&v);
}
static __device__ __forceinline__ void mma16816(float& d0, float& d1, float& d2, float& d3,
                                                uint32_t a0, uint32_t a1, uint32_t a2, uint32_t a3,
                                                uint32_t b0, uint32_t b1) {
    asm("mma.sync.aligned.m16n8k16.row.col.f32.f16.f16.f32 "
        "{%0,%1,%2,%3}, {%4,%5,%6,%7}, {%8,%9}, {%0,%1,%2,%3};"
        : "+f"(d0), "+f"(d1), "+f"(d2), "+f"(d3)
        : "r"(a0), "r"(a1), "r"(a2), "r"(a3), "r"(b0), "r"(b1));
}

// ---------------------------------------------------------------
// Kernel 1: h = node_feats @ W + b ; also fp16 transposed copy
// ---------------------------------------------------------------
__global__ __launch_bounds__(128) void k_proj(const float* __restrict__ nf,
                                              const float* __restrict__ W,
                                              const float* __restrict__ bias) {
    __shared__ float snf[16][CIN];
    const int t  = threadIdx.x;
    const int r0 = blockIdx.x * 16;
#pragma unroll
    for (int r = 0; r < 16; ++r)
        snf[r][t] = nf[(size_t)(r0 + r) * CIN + t];
    __syncthreads();

    float acc[16];
    const float bv = bias[t];
#pragma unroll
    for (int r = 0; r < 16; ++r) acc[r] = bv;

    for (int k4 = 0; k4 < CIN / 4; ++k4) {
        const float w0 = W[(k4 * 4 + 0) * HC + t];
        const float w1 = W[(k4 * 4 + 1) * HC + t];
        const float w2 = W[(k4 * 4 + 2) * HC + t];
        const float w3 = W[(k4 * 4 + 3) * HC + t];
#pragma unroll
        for (int r = 0; r < 16; ++r) {
            const float4 s = *(const float4*)&snf[r][k4 * 4];
            acc[r] = fmaf(s.x, w0, acc[r]);
            acc[r] = fmaf(s.y, w1, acc[r]);
            acc[r] = fmaf(s.z, w2, acc[r]);
            acc[r] = fmaf(s.w, w3, acc[r]);
        }
    }
#pragma unroll
    for (int r = 0; r < 16; ++r) {
        const int n  = r0 + r;
        const int b  = n >> 11;
        const int nn = n & (Nn - 1);
        g_h[(size_t)n * HC + t] = acc[r];
        g_hT[((size_t)b * HC + t) * Nn + nn] = __float2half(acc[r]);
    }
}

// ---------------------------------------------------------------
// Kernel 2: lp/lc per (n, head); F = 2^lc, F' = 2^(0.2 lc) in fp16
// ---------------------------------------------------------------
__global__ __launch_bounds__(256) void k_lplc(const float* __restrict__ a) {
    const int idx = blockIdx.x * 256 + threadIdx.x;
    const int n  = idx >> 4;
    const int hh = idx & 15;
    const float* hp = g_h + (size_t)n * HC + hh * Cc;
    const float* ap = a + hh * 2 * Cc;
    float lp = 0.f, lc = 0.f;
#pragma unroll
    for (int c = 0; c < Cc; ++c) {
        const float hv = hp[c];
        lp = fmaf(hv, ap[c],      lp);
        lc = fmaf(hv, ap[Cc + c], lc);
    }
    lp *= LOG2E; lc *= LOG2E;
    g_lp[idx] = lp;
    g_lc[idx] = lc;
    const int b  = n >> 11;
    const int nn = n & (Nn - 1);
    const size_t ti = ((size_t)b * Hh + hh) * Nn + nn;
    g_F [ti] = __float2half(ex2f(lc));
    g_Fp[ti] = __float2half(ex2f(0.2f * lc));
}

// ---------------------------------------------------------------
// Kernel 3: max_j lc'[b, j, h]
// ---------------------------------------------------------------
__global__ __launch_bounds__(256) void k_max() {
    const int b  = blockIdx.x >> 4;
    const int hh = blockIdx.x & 15;
    float m = -1e30f;
    for (int n = threadIdx.x; n < Nn; n += 256)
        m = fmaxf(m, g_lc[((size_t)b * Nn + n) * Hh + hh]);
    __shared__ float red[256];
    red[threadIdx.x] = m;
    __syncthreads();
    for (int s = 128; s; s >>= 1) {
        if (threadIdx.x < s)
            red[threadIdx.x] = fmaxf(red[threadIdx.x], red[threadIdx.x + s]);
        __syncthreads();
    }
    if (threadIdx.x == 0) g_mx[blockIdx.x] = red[0];
}

// ---------------------------------------------------------------
// Kernel 4: fused softmax-attention via mma.m16n8k16.
// Per-pair weight via factored exp:
//   w = adj * max(E_i*F_j, E'_i*F'_j)   (all fp16, HMUL2/HMAX2)
// No MUFU in the inner loop.
// ---------------------------------------------------------------
__global__ __launch_bounds__(512, 2) void k_main(const float* __restrict__ adj,
                                                 float* __restrict__ out,
                                                 int copy_adj) {
    __shared__ float sadj[2][16][ADJ_STRIDE];

    const int t    = threadIdx.x;
    const int warp = t >> 5;
    const int lane = t & 31;
    const int gid  = lane >> 2;   // 0..7
    const int tig  = lane & 3;    // 0..3
    const int hh   = warp;

    const int b  = blockIdx.x >> 7;          // 128 i-blocks per batch
    const int i0 = (blockIdx.x & 127) * 16;
    const size_t bN = (size_t)b * Nn;

    // per-row factors E = 2^(lp-m), E' = 2^(0.2lp-m)
    __half2 E0, E0p, E1, E1p;
    {
        const float mx  = g_mx[b * Hh + hh];
        const float lp0 = g_lp[(bN + i0 + gid)     * Hh + hh];
        const float lp1 = g_lp[(bN + i0 + gid + 8) * Hh + hh];
        const float s0 = lp0 + mx, s1 = lp1 + mx;
        const float m0 = fmaxf(s0, 0.2f * s0);
        const float m1 = fmaxf(s1, 0.2f * s1);
        E0  = __float2half2_rn(ex2f(lp0 - m0));
        E0p = __float2half2_rn(ex2f(0.2f * lp0 - m0));
        E1  = __float2half2_rn(ex2f(lp1 - m1));
        E1p = __float2half2_rn(ex2f(0.2f * lp1 - m1));
    }

    const __half*  Fb  = g_F  + ((size_t)b * Hh + hh) * Nn;
    const __half*  Fpb = g_Fp + ((size_t)b * Hh + hh) * Nn;
    const __half*  hTp = g_hT + ((size_t)b * HC + hh * Cc + gid) * Nn;
    const float*   adjrow = adj + (bN + i0) * (size_t)Nn;

    float dn0 = 0.f, dn1 = 0.f, dn2 = 0.f, dn3 = 0.f;   // numerator
    float dd0 = 0.f, dd1 = 0.f, dd2 = 0.f, dd3 = 0.f;   // denominator
    const uint32_t ONES = 0x3C003C00u;

    auto stage = [&](int jb, int bufi) {
        const int row = t >> 5, c4 = t & 31;
        const float* src = adjrow + (size_t)row * Nn + jb * 128 + c4 * 4;
        CP16(s2u(&sadj[bufi][row][c4 * 4]), src);
    };

    stage(0, 0);
    CP_COMMIT();

    for (int jb = 0; jb < NJB; ++jb) {
        if (jb + 1 < NJB) { stage(jb + 1, (jb + 1) & 1); CP_COMMIT(); CP_WAIT(1); }
        else              { CP_WAIT(0); }
        __syncthreads();
        const float (*sa)[ADJ_STRIDE] = sadj[jb & 1];

#pragma unroll 2
        for (int ks = 0; ks < 8; ++ks) {
            const int jc = ks * 16 + 2 * tig;
            const int j  = jb * 128 + jc;

            const __half2 F0  = *(const __half2*)(Fb  + j);
            const __half2 F1  = *(const __half2*)(Fb  + j + 8);
            const __half2 Fp0 = *(const __half2*)(Fpb + j);
            const __half2 Fp1 = *(const __half2*)(Fpb + j + 8);
            const uint32_t bh0 = *(const uint32_t*)(hTp + j);
            const uint32_t bh1 = *(const uint32_t*)(hTp + j + 8);

            const float2 a00 = *(const float2*)&sa[gid    ][jc];
            const float2 a01 = *(const float2*)&sa[gid    ][jc + 8];
            const float2 a10 = *(const float2*)&sa[gid + 8][jc];
            const float2 a11 = *(const float2*)&sa[gid + 8][jc + 8];
            __half2 m00, m01, m10, m11;
            *(uint32_t*)&m00 = packh2(a00.x, a00.y);
            *(uint32_t*)&m01 = packh2(a01.x, a01.y);
            *(uint32_t*)&m10 = packh2(a10.x, a10.y);
            *(uint32_t*)&m11 = packh2(a11.x, a11.y);

            const __half2 w0lo = __hmax2(__hmul2(F0, E0),  __hmul2(Fp0, E0p));
            const __half2 w1lo = __hmax2(__hmul2(F0, E1),  __hmul2(Fp0, E1p));
            const __half2 w0hi = __hmax2(__hmul2(F1, E0),  __hmul2(Fp1, E0p));
            const __half2 w1hi = __hmax2(__hmul2(F1, E1),  __hmul2(Fp1, E1p));

            const uint32_t ra0 = h2b(__hmul2(w0lo, m00));
            const uint32_t ra1 = h2b(__hmul2(w1lo, m10));
            const uint32_t ra2 = h2b(__hmul2(w0hi, m01));
            const uint32_t ra3 = h2b(__hmul2(w1hi, m11));

            mma16816(dn0, dn1, dn2, dn3, ra0, ra1, ra2, ra3, bh0, bh1);
            mma16816(dd0, dd1, dd2, dd3, ra0, ra1, ra2, ra3, ONES, ONES);
        }
        __syncthreads();
    }

    // ---- epilogue: divide and store ----
    {
        const float inv0 = 1.0f / dd0;   // row r0
        const float inv1 = 1.0f / dd2;   // row r1
        float2 o0 = make_float2(dn0 * inv0, dn1 * inv0);
        float2 o1 = make_float2(dn2 * inv1, dn3 * inv1);
        *(float2*)(out + (bN + i0 + gid)     * HC + hh * Cc + 2 * tig) = o0;
        *(float2*)(out + (bN + i0 + gid + 8) * HC + hh * Cc + 2 * tig) = o1;
    }

    // ---- fold adj tail copy into this kernel ----
    if (copy_adj) {
        float* dst = out + (size_t)Bn * Nn * HC + (bN + i0) * (size_t)Nn;
        const float4* s4 = (const float4*)adjrow;
        float4* d4 = (float4*)dst;
#pragma unroll
        for (int q = 0; q < 16; ++q)
            d4[q * 512 + t] = s4[q * 512 + t];
    }
}

// ---------------------------------------------------------------
extern "C" void kernel_launch(void* const* d_in, const int* in_sizes, int n_in,
                              void* d_out, int out_size) {
    const float* nf   = (const float*)d_in[0];
    const float* adj  = (const float*)d_in[1];
    const float* W    = (const float*)d_in[2];
    const float* bias = (const float*)d_in[3];
    const float* a    = (const float*)d_in[4];
    float* out = (float*)d_out;

    const long long outel = (long long)Bn * Nn * HC;        // 524288
    const long long adjel = (long long)Bn * Nn * Nn;        // 8388608
    const int copy_adj = ((long long)out_size >= outel + adjel) ? 1 : 0;

    k_proj<<<Bn * Nn / 16, 128>>>(nf, W, bias);
    k_lplc<<<Bn * Nn * Hh / 256, 256>>>(a);
    k_max<<<Bn * Hh, 256>>>();
    k_main<<<Bn * (Nn / 16), 512>>>(adj, out, copy_adj);
}

// round 5
// speedup vs baseline: 2.7673x; 1.0033x over previous
#include <cuda_runtime.h>
#include <cuda_fp16.h>
#include <cstdint>

#define Bn   2
#define Nn   2048
#define CIN  128
#define Hh   16
#define Cc   8
#define HC   128
#define LOG2E 1.4426950408889634f
#define NJB  16          // j-blocks of 128
#define SDH  136         // adj tile row stride in halves

// ---- device scratch ----
__device__ __half   g_adjh[Bn * Nn * Nn];  // fp16 adjacency
__device__ __half   g_hT [Bn * HC * Nn];   // [b][f][n] fp16, transposed
__device__ float    g_lp [Bn * Nn * Hh];   // lp * log2e
__device__ __half2  g_FF [Bn * Hh * Nn];   // (2^lc, 2^(0.2lc)) per node
__device__ unsigned g_mxu[Bn * Hh];        // encoded max_j lc'

// ---- PTX helpers ----
#define CP16(dst, src) asm volatile("cp.async.cg.shared.global [%0], [%1], 16;" :: "r"(dst), "l"(src))
#define CP_COMMIT()    asm volatile("cp.async.commit_group;")
#define CP_WAIT(n)     asm volatile("cp.async.wait_group %0;" :: "n"(n))

static __device__ __forceinline__ uint32_t s2u(const void* p) {
    return (uint32_t)__cvta_generic_to_shared(p);
}
static __device__ __forceinline__ float ex2f(float x) {
    float r; asm("ex2.approx.f32 %0, %1;" : "=f"(r) : "f"(x)); return r;
}
static __device__ __forceinline__ uint32_t prmtb(uint32_t a, uint32_t b, uint32_t sel) {
    uint32_t d; asm("prmt.b32 %0, %1, %2, %3;" : "=r"(d) : "r"(a), "r"(b), "r"(sel)); return d;
}
static __device__ __forceinline__ uint32_t h2b(__half2 v) {
    return *reinterpret_cast<uint32_t*>(&v);
}
static __device__ __forceinline__ __half2 b2h(uint32_t u) {
    return *reinterpret_cast<__half2*>(&u);
}
static __device__ __forceinline__ unsigned encf(float f) {
    int i = __float_as_int(f);
    return (i >= 0) ? ((unsigned)i | 0x80000000u) : ~(unsigned)i;
}
static __device__ __forceinline__ float decf(unsigned u) {
    int i = (u & 0x80000000u) ? (int)(u & 0x7FFFFFFFu) : (int)~u;
    return __int_as_float(i);
}
static __device__ __forceinline__ void mma16816(float& d0, float& d1, float& d2, float& d3,
                                                uint32_t a0, uint32_t a1, uint32_t a2, uint32_t a3,
                                                uint32_t b0, uint32_t b1) {
    asm("mma.sync.aligned.m16n8k16.row.col.f32.f16.f16.f32 "
        "{%0,%1,%2,%3}, {%4,%5,%6,%7}, {%8,%9}, {%0,%1,%2,%3};"
        : "+f"(d0), "+f"(d1), "+f"(d2), "+f"(d3)
        : "r"(a0), "r"(a1), "r"(a2), "r"(a3), "r"(b0), "r"(b1));
}

// ---------------------------------------------------------------
// Kernel A: adj fp32 -> fp16, plus g_mxu reset. Runs first.
// ---------------------------------------------------------------
__global__ __launch_bounds__(256) void k_adj(const float* __restrict__ adj) {
    if (blockIdx.x == 0 && threadIdx.x < Bn * Hh)
        g_mxu[threadIdx.x] = 0u;
    const size_t i = ((size_t)blockIdx.x * 256 + threadIdx.x) * 4;
    const float4 v = *(const float4*)(adj + i);
    const __half2 lo = __floats2half2_rn(v.x, v.y);
    const __half2 hi = __floats2half2_rn(v.z, v.w);
    *(uint2*)(g_adjh + i) = make_uint2(h2b(lo), h2b(hi));
}

// ---------------------------------------------------------------
// Kernel B: projection + per-node logits, fused.
//   h = nf @ W + b (fp32), hT fp16; lp' = log2e*a_p.h; lc' = log2e*a_c.h;
//   g_FF = (2^lc', 2^(0.2lc')); g_mxu = max over nodes (atomic).
// ---------------------------------------------------------------
__global__ __launch_bounds__(128) void k_proj(const float* __restrict__ nf,
                                              const float* __restrict__ W,
                                              const float* __restrict__ bias,
                                              const float* __restrict__ a) {
    __shared__ float snf[16][CIN];
    __shared__ float sred[Hh][17];
    const int t  = threadIdx.x;
    const int r0 = blockIdx.x * 16;
#pragma unroll
    for (int r = 0; r < 16; ++r)
        snf[r][t] = nf[(size_t)(r0 + r) * CIN + t];
    __syncthreads();

    float acc[16];
    const float bv = bias[t];
#pragma unroll
    for (int r = 0; r < 16; ++r) acc[r] = bv;

    for (int k4 = 0; k4 < CIN / 4; ++k4) {
        const float w0 = W[(k4 * 4 + 0) * HC + t];
        const float w1 = W[(k4 * 4 + 1) * HC + t];
        const float w2 = W[(k4 * 4 + 2) * HC + t];
        const float w3 = W[(k4 * 4 + 3) * HC + t];
#pragma unroll
        for (int r = 0; r < 16; ++r) {
            const float4 s = *(const float4*)&snf[r][k4 * 4];
            acc[r] = fmaf(s.x, w0, acc[r]);
            acc[r] = fmaf(s.y, w1, acc[r]);
            acc[r] = fmaf(s.z, w2, acc[r]);
            acc[r] = fmaf(s.w, w3, acc[r]);
        }
    }

    const int b  = r0 >> 11;               // whole block within one batch
    const int n0 = r0 & (Nn - 1);
#pragma unroll
    for (int r = 0; r < 16; ++r)
        g_hT[((size_t)b * HC + t) * Nn + n0 + r] = __float2half(acc[r]);

    __syncthreads();                       // all GEMM reads of snf done
#pragma unroll
    for (int r = 0; r < 16; ++r)
        snf[r][t] = acc[r];                // snf now holds h
    __syncthreads();

    // lp/lc for 2 (row, head) tasks per thread
    const int rr = t >> 3;
    const int hb = (t & 7) * 2;
#pragma unroll
    for (int p = 0; p < 2; ++p) {
        const int h = hb + p;
        const float* hv = &snf[rr][h * Cc];
        const float* ap = a + h * 2 * Cc;
        float lp = 0.f, lc = 0.f;
#pragma unroll
        for (int c = 0; c < Cc; ++c) {
            lp = fmaf(hv[c], ap[c],      lp);
            lc = fmaf(hv[c], ap[Cc + c], lc);
        }
        lp *= LOG2E; lc *= LOG2E;
        const int n = r0 + rr;
        g_lp[n * Hh + h] = lp;
        g_FF[((size_t)b * Hh + h) * Nn + (n & (Nn - 1))] =
            __halves2half2(__float2half(ex2f(lc)), __float2half(ex2f(0.2f * lc)));
        sred[h][rr] = lc;
    }
    __syncthreads();
    if (t < Hh) {
        float m = sred[t][0];
#pragma unroll
        for (int r = 1; r < 16; ++r) m = fmaxf(m, sred[t][r]);
        atomicMax(&g_mxu[b * Hh + t], encf(m));
    }
}

// ---------------------------------------------------------------
// Kernel C: fused softmax-attention via mma.m16n8k16.
//   w = adj * max(E_i F_j, E'_i F'_j), everything fp16; adj staged fp16.
// ---------------------------------------------------------------
__global__ __launch_bounds__(512, 2) void k_main(const float* __restrict__ adj,
                                                 float* __restrict__ out,
                                                 int copy_adj) {
    __shared__ __half sah[2][16][SDH];

    const int t    = threadIdx.x;
    const int warp = t >> 5;
    const int lane = t & 31;
    const int gid  = lane >> 2;   // 0..7
    const int tig  = lane & 3;    // 0..3
    const int hh   = warp;

    const int b  = blockIdx.x >> 7;
    const int i0 = (blockIdx.x & 127) * 16;
    const size_t bN = (size_t)b * Nn;

    // per-row factors E = 2^(lp-m), E' = 2^(0.2lp-m)
    __half2 E0, E0p, E1, E1p;
    {
        const float mx  = decf(g_mxu[b * Hh + hh]);
        const float lp0 = g_lp[(bN + i0 + gid)     * Hh + hh];
        const float lp1 = g_lp[(bN + i0 + gid + 8) * Hh + hh];
        const float s0 = lp0 + mx, s1 = lp1 + mx;
        const float m0 = fmaxf(s0, 0.2f * s0);
        const float m1 = fmaxf(s1, 0.2f * s1);
        E0  = __float2half2_rn(ex2f(lp0 - m0));
        E0p = __float2half2_rn(ex2f(0.2f * lp0 - m0));
        E1  = __float2half2_rn(ex2f(lp1 - m1));
        E1p = __float2half2_rn(ex2f(0.2f * lp1 - m1));
    }

    const __half2* FFb = g_FF + ((size_t)b * Hh + hh) * Nn;
    const __half*  hTp = g_hT + ((size_t)b * HC + hh * Cc + gid) * Nn;
    const __half*  adjh = g_adjh + (bN + i0) * (size_t)Nn;
    const float*   adjrow = adj + (bN + i0) * (size_t)Nn;

    float dn0 = 0.f, dn1 = 0.f, dn2 = 0.f, dn3 = 0.f;
    float dd0 = 0.f, dd1 = 0.f, dd2 = 0.f, dd3 = 0.f;
    const uint32_t ONES = 0x3C003C00u;

    auto stage = [&](int jb, int bufi) {
        if (t < 256) {
            const int row = t >> 4, seg = t & 15;
            const __half* src = adjh + (size_t)row * Nn + jb * 128 + seg * 8;
            CP16(s2u(&sah[bufi][row][seg * 8]), src);
        }
    };

    stage(0, 0);
    CP_COMMIT();

    for (int jb = 0; jb < NJB; ++jb) {
        if (jb + 1 < NJB) { stage(jb + 1, (jb + 1) & 1); CP_COMMIT(); CP_WAIT(1); }
        else              { CP_WAIT(0); }
        __syncthreads();
        const __half (*sa)[SDH] = sah[jb & 1];

#pragma unroll 2
        for (int ks = 0; ks < 8; ++ks) {
            const int jc = ks * 16 + 2 * tig;
            const int j  = jb * 128 + jc;

            const uint2 ffl = *(const uint2*)(FFb + j);       // (F,F')_{j},(F,F')_{j+1}
            const uint2 ffh = *(const uint2*)(FFb + j + 8);
            const uint32_t F0  = prmtb(ffl.x, ffl.y, 0x5410);
            const uint32_t Fp0 = prmtb(ffl.x, ffl.y, 0x7632);
            const uint32_t F1  = prmtb(ffh.x, ffh.y, 0x5410);
            const uint32_t Fp1 = prmtb(ffh.x, ffh.y, 0x7632);
            const uint32_t bh0 = *(const uint32_t*)(hTp + j);
            const uint32_t bh1 = *(const uint32_t*)(hTp + j + 8);

            const __half2 m00 = *(const __half2*)&sa[gid    ][jc];
            const __half2 m01 = *(const __half2*)&sa[gid    ][jc + 8];
            const __half2 m10 = *(const __half2*)&sa[gid + 8][jc];
            const __half2 m11 = *(const __half2*)&sa[gid + 8][jc + 8];

            const __half2 w0lo = __hmax2(__hmul2(b2h(F0),  E0),  __hmul2(b2h(Fp0), E0p));
            const __half2 w1lo = __hmax2(__hmul2(b2h(F0),  E1),  __hmul2(b2h(Fp0), E1p));
            const __half2 w0hi = __hmax2(__hmul2(b2h(F1),  E0),  __hmul2(b2h(Fp1), E0p));
            const __half2 w1hi = __hmax2(__hmul2(b2h(F1),  E1),  __hmul2(b2h(Fp1), E1p));

            const uint32_t ra0 = h2b(__hmul2(w0lo, m00));
            const uint32_t ra1 = h2b(__hmul2(w1lo, m10));
            const uint32_t ra2 = h2b(__hmul2(w0hi, m01));
            const uint32_t ra3 = h2b(__hmul2(w1hi, m11));

            mma16816(dn0, dn1, dn2, dn3, ra0, ra1, ra2, ra3, bh0, bh1);
            mma16816(dd0, dd1, dd2, dd3, ra0, ra1, ra2, ra3, ONES, ONES);
        }
        __syncthreads();
    }

    // ---- epilogue: divide and store ----
    {
        const float inv0 = 1.0f / dd0;
        const float inv1 = 1.0f / dd2;
        float2 o0 = make_float2(dn0 * inv0, dn1 * inv0);
        float2 o1 = make_float2(dn2 * inv1, dn3 * inv1);
        *(float2*)(out + (bN + i0 + gid)     * HC + hh * Cc + 2 * tig) = o0;
        *(float2*)(out + (bN + i0 + gid + 8) * HC + hh * Cc + 2 * tig) = o1;
    }

    // ---- fold adj tail copy into this kernel ----
    if (copy_adj) {
        float* dst = out + (size_t)Bn * Nn * HC + (bN + i0) * (size_t)Nn;
        const float4* s4 = (const float4*)adjrow;
        float4* d4 = (float4*)dst;
#pragma unroll
        for (int q = 0; q < 16; ++q)
            d4[q * 512 + t] = s4[q * 512 + t];
    }
}

// ---------------------------------------------------------------
extern "C" void kernel_launch(void* const* d_in, const int* in_sizes, int n_in,
                              void* d_out, int out_size) {
    const float* nf   = (const float*)d_in[0];
    const float* adj  = (const float*)d_in[1];
    const float* W    = (const float*)d_in[2];
    const float* bias = (const float*)d_in[3];
    const float* a    = (const float*)d_in[4];
    float* out = (float*)d_out;

    const long long outel = (long long)Bn * Nn * HC;        // 524288
    const long long adjel = (long long)Bn * Nn * Nn;        // 8388608
    const int copy_adj = ((long long)out_size >= outel + adjel) ? 1 : 0;

    k_adj <<<(int)(adjel / 1024), 256>>>(adj);
    k_proj<<<Bn * Nn / 16, 128>>>(nf, W, bias, a);
    k_main<<<Bn * (Nn / 16), 512>>>(adj, out, copy_adj);
}

// round 6
// speedup vs baseline: 3.2369x; 1.1697x over previous
#include <cuda_runtime.h>
#include <cuda_fp16.h>
#include <cstdint>

#define Bn   2
#define Nn   2048
#define CIN  128
#define Hh   16
#define Cc   8
#define HC   128
#define LOG2E 1.4426950408889634f
#define NJB  16          // j-blocks of 128
#define SDH  136         // adj tile row stride in halves

// dynamic smem carve (halves): H tiles 2x16384, adj tiles 2x(16*136)
#define SH_H   16384
#define SH_A   (16 * SDH)
#define SMEM_HALVES (2 * SH_H + 2 * SH_A)
#define SMEM_BYTES  (SMEM_HALVES * 2)

// ---- device scratch ----
__device__ __half   g_adjh[Bn * Nn * Nn];  // fp16 adjacency
__device__ __half   g_hT [Bn * HC * Nn];   // [b][f][n] fp16, transposed
__device__ float    g_lp [Bn * Nn * Hh];   // lp * log2e
__device__ __half2  g_FF [Bn * Hh * Nn];   // (2^lc, 2^(0.2lc)) per node
__device__ unsigned g_mxu[Bn * Hh];        // encoded max_j lc'

// ---- PTX helpers ----
#define CP16(dst, src) asm volatile("cp.async.cg.shared.global [%0], [%1], 16;" :: "r"(dst), "l"(src))
#define CP_COMMIT()    asm volatile("cp.async.commit_group;")
#define CP_WAIT(n)     asm volatile("cp.async.wait_group %0;" :: "n"(n))

static __device__ __forceinline__ uint32_t s2u(const void* p) {
    return (uint32_t)__cvta_generic_to_shared(p);
}
static __device__ __forceinline__ float ex2f(float x) {
    float r; asm("ex2.approx.f32 %0, %1;" : "=f"(r) : "f"(x)); return r;
}
static __device__ __forceinline__ uint32_t prmtb(uint32_t a, uint32_t b, uint32_t sel) {
    uint32_t d; asm("prmt.b32 %0, %1, %2, %3;" : "=r"(d) : "r"(a), "r"(b), "r"(sel)); return d;
}
static __device__ __forceinline__ uint32_t h2b(__half2 v) {
    return *reinterpret_cast<uint32_t*>(&v);
}
static __device__ __forceinline__ __half2 b2h(uint32_t u) {
    return *reinterpret_cast<__half2*>(&u);
}
static __device__ __forceinline__ unsigned encf(float f) {
    int i = __float_as_int(f);
    return (i >= 0) ? ((unsigned)i | 0x80000000u) : ~(unsigned)i;
}
static __device__ __forceinline__ float decf(unsigned u) {
    int i = (u & 0x80000000u) ? (int)(u & 0x7FFFFFFFu) : (int)~u;
    return __int_as_float(i);
}
static __device__ __forceinline__ void mma16816(float& d0, float& d1, float& d2, float& d3,
                                                uint32_t a0, uint32_t a1, uint32_t a2, uint32_t a3,
                                                uint32_t b0, uint32_t b1) {
    asm("mma.sync.aligned.m16n8k16.row.col.f32.f16.f16.f32 "
        "{%0,%1,%2,%3}, {%4,%5,%6,%7}, {%8,%9}, {%0,%1,%2,%3};"
        : "+f"(d0), "+f"(d1), "+f"(d2), "+f"(d3)
        : "r"(a0), "r"(a1), "r"(a2), "r"(a3), "r"(b0), "r"(b1));
}

// ---------------------------------------------------------------
// Kernel A: one pass over fp32 adj — emit fp16 adj AND the fp32
// out-tail copy; also reset g_mxu. Runs first.
// ---------------------------------------------------------------
__global__ __launch_bounds__(256) void k_adj(const float* __restrict__ adj,
                                             float* __restrict__ out_tail,
                                             int copy_adj) {
    if (blockIdx.x == 0 && threadIdx.x < Bn * Hh)
        g_mxu[threadIdx.x] = 0u;
    const size_t i = ((size_t)blockIdx.x * 256 + threadIdx.x) * 4;
    const float4 v = *(const float4*)(adj + i);
    const __half2 lo = __floats2half2_rn(v.x, v.y);
    const __half2 hi = __floats2half2_rn(v.z, v.w);
    *(uint2*)(g_adjh + i) = make_uint2(h2b(lo), h2b(hi));
    if (copy_adj)
        *(float4*)(out_tail + i) = v;
}

// ---------------------------------------------------------------
// Kernel B: projection + per-node logits, fused.
// ---------------------------------------------------------------
__global__ __launch_bounds__(128) void k_proj(const float* __restrict__ nf,
                                              const float* __restrict__ W,
                                              const float* __restrict__ bias,
                                              const float* __restrict__ a) {
    __shared__ float snf[16][132];
    __shared__ float sred[Hh][17];
    const int t  = threadIdx.x;
    const int r0 = blockIdx.x * 16;
#pragma unroll
    for (int r = 0; r < 16; ++r)
        snf[r][t] = nf[(size_t)(r0 + r) * CIN + t];
    __syncthreads();

    float acc[16];
    const float bv = bias[t];
#pragma unroll
    for (int r = 0; r < 16; ++r) acc[r] = bv;

    for (int k4 = 0; k4 < CIN / 4; ++k4) {
        const float w0 = W[(k4 * 4 + 0) * HC + t];
        const float w1 = W[(k4 * 4 + 1) * HC + t];
        const float w2 = W[(k4 * 4 + 2) * HC + t];
        const float w3 = W[(k4 * 4 + 3) * HC + t];
#pragma unroll
        for (int r = 0; r < 16; ++r) {
            const float4 s = *(const float4*)&snf[r][k4 * 4];
            acc[r] = fmaf(s.x, w0, acc[r]);
            acc[r] = fmaf(s.y, w1, acc[r]);
            acc[r] = fmaf(s.z, w2, acc[r]);
            acc[r] = fmaf(s.w, w3, acc[r]);
        }
    }

    const int b  = r0 >> 11;
    const int n0 = r0 & (Nn - 1);

    // hT write: thread t == feature f; acc[] is 16 consecutive n-values.
    {
        __half hv[16];
#pragma unroll
        for (int r = 0; r < 16; ++r) hv[r] = __float2half(acc[r]);
        uint4* dst = (uint4*)(g_hT + ((size_t)b * HC + t) * Nn + n0);
        dst[0] = *(const uint4*)&hv[0];
        dst[1] = *(const uint4*)&hv[8];
    }

    __syncthreads();
#pragma unroll
    for (int r = 0; r < 16; ++r)
        snf[r][t] = acc[r];                // snf now holds h
    __syncthreads();

    // lp/lc for 2 (row, head) tasks per thread
    const int rr = t >> 3;
    const int hb = (t & 7) * 2;
#pragma unroll
    for (int p = 0; p < 2; ++p) {
        const int h = hb + p;
        const float* hv = &snf[rr][h * Cc];
        const float* ap = a + h * 2 * Cc;
        float lp = 0.f, lc = 0.f;
#pragma unroll
        for (int c = 0; c < Cc; ++c) {
            lp = fmaf(hv[c], ap[c],      lp);
            lc = fmaf(hv[c], ap[Cc + c], lc);
        }
        lp *= LOG2E; lc *= LOG2E;
        const int n = r0 + rr;
        g_lp[n * Hh + h] = lp;
        g_FF[((size_t)b * Hh + h) * Nn + (n & (Nn - 1))] =
            __halves2half2(__float2half(ex2f(lc)), __float2half(ex2f(0.2f * lc)));
        sred[h][rr] = lc;
    }
    __syncthreads();
    if (t < Hh) {
        float m = sred[t][0];
#pragma unroll
        for (int r = 1; r < 16; ++r) m = fmaxf(m, sred[t][r]);
        atomicMax(&g_mxu[b * Hh + t], encf(m));
    }
}

// ---------------------------------------------------------------
// Kernel C: fused softmax-attention via mma.m16n8k16.
// H tile staged in smem (chunk-XOR swizzle) -> conflict-free LDS.32
// B-fragment loads. adj staged fp16. No MUFU in the loop.
// ---------------------------------------------------------------
__global__ __launch_bounds__(512, 2) void k_main(float* __restrict__ out) {
    extern __shared__ __align__(16) __half smem[];
    __half* const sH[2] = { smem, smem + SH_H };
    __half* const sA[2] = { smem + 2 * SH_H, smem + 2 * SH_H + SH_A };

    const int t    = threadIdx.x;
    const int warp = t >> 5;
    const int lane = t & 31;
    const int gid  = lane >> 2;   // 0..7
    const int tig  = lane & 3;    // 0..3
    const int hh   = warp;

    const int b  = blockIdx.x >> 7;
    const int i0 = (blockIdx.x & 127) * 16;
    const size_t bN = (size_t)b * Nn;

    // per-row factors E = 2^(lp-m), E' = 2^(0.2lp-m)
    __half2 E0, E0p, E1, E1p;
    {
        const float mx  = decf(g_mxu[b * Hh + hh]);
        const float lp0 = g_lp[(bN + i0 + gid)     * Hh + hh];
        const float lp1 = g_lp[(bN + i0 + gid + 8) * Hh + hh];
        const float s0 = lp0 + mx, s1 = lp1 + mx;
        const float m0 = fmaxf(s0, 0.2f * s0);
        const float m1 = fmaxf(s1, 0.2f * s1);
        E0  = __float2half2_rn(ex2f(lp0 - m0));
        E0p = __float2half2_rn(ex2f(0.2f * lp0 - m0));
        E1  = __float2half2_rn(ex2f(lp1 - m1));
        E1p = __float2half2_rn(ex2f(0.2f * lp1 - m1));
    }

    const __half2* FFb  = g_FF + ((size_t)b * Hh + hh) * Nn;
    const __half*  hTb  = g_hT + (size_t)b * HC * Nn;
    const __half*  adjh = g_adjh + (bN + i0) * (size_t)Nn;

    float dn0 = 0.f, dn1 = 0.f, dn2 = 0.f, dn3 = 0.f;
    float dd0 = 0.f, dd1 = 0.f, dd2 = 0.f, dd3 = 0.f;
    const uint32_t ONES = 0x3C003C00u;

    auto stage = [&](int jb, int bufi) {
        __half* hbuf = sH[bufi];
        __half* abuf = sA[bufi];
#pragma unroll
        for (int q = 0; q < 4; ++q) {
            const int id = q * 512 + t;        // 0..2047
            const int f  = id >> 4;
            const int c  = id & 15;
            const __half* src = hTb + (size_t)f * Nn + jb * 128 + c * 8;
            CP16(s2u(hbuf + f * 128 + ((c ^ (f & 7)) << 3)), src);
        }
        if (t < 256) {
            const int row = t >> 4, seg = t & 15;
            const __half* src = adjh + (size_t)row * Nn + jb * 128 + seg * 8;
            CP16(s2u(abuf + row * SDH + seg * 8), src);
        }
    };

    stage(0, 0);
    CP_COMMIT();

    for (int jb = 0; jb < NJB; ++jb) {
        if (jb + 1 < NJB) { stage(jb + 1, (jb + 1) & 1); CP_COMMIT(); CP_WAIT(1); }
        else              { CP_WAIT(0); }
        __syncthreads();
        const __half* hbuf = sH[jb & 1];
        const __half* abuf = sA[jb & 1];
        const __half* Hrow = hbuf + (hh * 8 + gid) * 128;

#pragma unroll 2
        for (int ks = 0; ks < 8; ++ks) {
            const int jc = ks * 16 + 2 * tig;
            const int j  = jb * 128 + jc;

            const uint2 ffl = *(const uint2*)(FFb + j);
            const uint2 ffh = *(const uint2*)(FFb + j + 8);
            const uint32_t F0  = prmtb(ffl.x, ffl.y, 0x5410);
            const uint32_t Fp0 = prmtb(ffl.x, ffl.y, 0x7632);
            const uint32_t F1  = prmtb(ffh.x, ffh.y, 0x5410);
            const uint32_t Fp1 = prmtb(ffh.x, ffh.y, 0x7632);

            const uint32_t bh0 = *(const uint32_t*)(Hrow + (((2*ks)   ^ gid) << 3) + 2 * tig);
            const uint32_t bh1 = *(const uint32_t*)(Hrow + (((2*ks+1) ^ gid) << 3) + 2 * tig);

            const __half2 m00 = *(const __half2*)(abuf + gid       * SDH + jc);
            const __half2 m01 = *(const __half2*)(abuf + gid       * SDH + jc + 8);
            const __half2 m10 = *(const __half2*)(abuf + (gid + 8) * SDH + jc);
            const __half2 m11 = *(const __half2*)(abuf + (gid + 8) * SDH + jc + 8);

            const __half2 w0lo = __hmax2(__hmul2(b2h(F0),  E0),  __hmul2(b2h(Fp0), E0p));
            const __half2 w1lo = __hmax2(__hmul2(b2h(F0),  E1),  __hmul2(b2h(Fp0), E1p));
            const __half2 w0hi = __hmax2(__hmul2(b2h(F1),  E0),  __hmul2(b2h(Fp1), E0p));
            const __half2 w1hi = __hmax2(__hmul2(b2h(F1),  E1),  __hmul2(b2h(Fp1), E1p));

            const uint32_t ra0 = h2b(__hmul2(w0lo, m00));
            const uint32_t ra1 = h2b(__hmul2(w1lo, m10));
            const uint32_t ra2 = h2b(__hmul2(w0hi, m01));
            const uint32_t ra3 = h2b(__hmul2(w1hi, m11));

            mma16816(dn0, dn1, dn2, dn3, ra0, ra1, ra2, ra3, bh0, bh1);
            mma16816(dd0, dd1, dd2, dd3, ra0, ra1, ra2, ra3, ONES, ONES);
        }
        __syncthreads();
    }

    // ---- epilogue: divide and store ----
    {
        const float inv0 = 1.0f / dd0;
        const float inv1 = 1.0f / dd2;
        float2 o0 = make_float2(dn0 * inv0, dn1 * inv0);
        float2 o1 = make_float2(dn2 * inv1, dn3 * inv1);
        *(float2*)(out + (bN + i0 + gid)     * HC + hh * Cc + 2 * tig) = o0;
        *(float2*)(out + (bN + i0 + gid + 8) * HC + hh * Cc + 2 * tig) = o1;
    }
}

// ---------------------------------------------------------------
extern "C" void kernel_launch(void* const* d_in, const int* in_sizes, int n_in,
                              void* d_out, int out_size) {
    const float* nf   = (const float*)d_in[0];
    const float* adj  = (const float*)d_in[1];
    const float* W    = (const float*)d_in[2];
    const float* bias = (const float*)d_in[3];
    const float* a    = (const float*)d_in[4];
    float* out = (float*)d_out;

    const long long outel = (long long)Bn * Nn * HC;        // 524288
    const long long adjel = (long long)Bn * Nn * Nn;        // 8388608
    const int copy_adj = ((long long)out_size >= outel + adjel) ? 1 : 0;

    cudaFuncSetAttribute(k_main, cudaFuncAttributeMaxDynamicSharedMemorySize,
                         SMEM_BYTES);

    k_adj <<<(int)(adjel / 1024), 256>>>(adj, out + outel, copy_adj);
    k_proj<<<Bn * Nn / 16, 128>>>(nf, W, bias, a);
    k_main<<<Bn * (Nn / 16), 512, SMEM_BYTES>>>(out);
}